// round 2
// baseline (speedup 1.0000x reference)
#include <cuda_runtime.h>

#define QSCALE 0.17677669529663687f   // 32^-0.5

typedef unsigned long long u64;

// ---------------------------------------------------------------------------
// Scratch (static device arrays; no allocation allowed)
// ---------------------------------------------------------------------------
__device__ __align__(16) float g_wt [1152 * 1024];        // K-major weights [k][co]
__device__ __align__(16) float g_q  [32 * 1024 * 32];     // [bh][pos][d] (scaled)
__device__ __align__(16) float g_k  [32 * 1024 * 32];
__device__ __align__(16) float g_v  [32 * 1024 * 32];
__device__ __align__(16) float g_rx [32 * 1024 * 32];     // [bh][i][jc]
__device__ __align__(16) float g_ry [32 * 1024 * 32];     // [bh][i][jr]
__device__ __align__(16) float g_att[4 * 256 * 1024];     // scrambled-channel att

// ---------------------------------------------------------------------------
// f32x2 packed helpers
// ---------------------------------------------------------------------------
__device__ __forceinline__ u64 pk2(float lo, float hi) {
    u64 r; asm("mov.b64 %0,{%1,%2};" : "=l"(r) : "f"(lo), "f"(hi)); return r;
}
__device__ __forceinline__ void upk2(float& lo, float& hi, u64 v) {
    asm("mov.b64 {%0,%1},%2;" : "=f"(lo), "=f"(hi) : "l"(v));
}
__device__ __forceinline__ void ffma2(u64& d, u64 a, u64 b) {
    asm("fma.rn.f32x2 %0,%1,%2,%0;" : "+l"(d) : "l"(a), "l"(b));
}
__device__ __forceinline__ u64 fmul2(u64 a, u64 b) {
    u64 d; asm("mul.rn.f32x2 %0,%1,%2;" : "=l"(d) : "l"(a), "l"(b)); return d;
}

// ---------------------------------------------------------------------------
// K0: weight transpose -> K-major [k][co]; co 0..255 = conv_w, 256..1023 = qkv_w
// ---------------------------------------------------------------------------
__global__ void k_wt(const float* __restrict__ cw, const float* __restrict__ qw) {
    int idx = blockIdx.x * 256 + threadIdx.x;      // 1152*1024 total
    int k  = idx >> 10;
    int co = idx & 1023;
    g_wt[idx] = (co < 256) ? cw[co * 1152 + k] : qw[(co - 256) * 1152 + k];
}

// ---------------------------------------------------------------------------
// K1: fused 3x3 conv. Block: 128 co x 64 pos (2 rows). 256 thr, tile 8co x 4pos.
// ---------------------------------------------------------------------------
__global__ __launch_bounds__(256) void k_conv(const float* __restrict__ x,
                                              const float* __restrict__ cb,
                                              const float* __restrict__ qb,
                                              float* __restrict__ out) {
    __shared__ __align__(16) float Ws[72 * 128];   // [ci_l*9+tap][co_l]
    __shared__ float Xs[8 * 4 * 37];               // [ci_l][row][col(-1..35)]

    const int tid = threadIdx.x;
    const int b   = blockIdx.x >> 4;
    const int y0  = (blockIdx.x & 15) << 1;
    const int co_base = blockIdx.y << 7;
    const int cg = tid >> 4, pg = tid & 15;
    const int ly = pg >> 3, lx0 = (pg & 7) << 2;
    const int co0 = co_base + cg * 8;

    u64 acc[4][4];
#pragma unroll
    for (int a = 0; a < 4; a++)
#pragma unroll
        for (int c = 0; c < 4; c++) acc[a][c] = 0ULL;

    for (int ch = 0; ch < 16; ch++) {
        const int ci0 = ch << 3;
        __syncthreads();
        for (int t = tid; t < 72 * 32; t += 256) {
            int row = t >> 5, f = t & 31;
            *(float4*)&Ws[row * 128 + f * 4] =
                *(const float4*)&g_wt[(size_t)(ci0 * 9 + row) * 1024 + co_base + f * 4];
        }
        for (int t = tid; t < 1184; t += 256) {
            int ci  = t / 148;
            int rem = t - ci * 148;
            int rr  = rem / 37;
            int c   = rem - rr * 37;
            int gy = y0 - 1 + rr;
            int gx = c - 1;
            float v = 0.f;
            if (gy >= 0 && gy < 32 && (unsigned)gx < 32u)
                v = x[(size_t)((b * 128 + ci0 + ci) * 32 + gy) * 32 + gx];
            Xs[t] = v;
        }
        __syncthreads();
#pragma unroll
        for (int ci = 0; ci < 8; ci++) {
#pragma unroll
            for (int ky = 0; ky < 3; ky++) {
                const float* xp = Xs + ci * 148 + (ly + ky) * 37 + lx0;
                u64 xb[6];
#pragma unroll
                for (int t = 0; t < 6; t++) { float xv = xp[t]; xb[t] = pk2(xv, xv); }
#pragma unroll
                for (int kx = 0; kx < 3; kx++) {
                    const ulonglong2* wp =
                        (const ulonglong2*)(Ws + (ci * 9 + ky * 3 + kx) * 128 + cg * 8);
                    ulonglong2 wA = wp[0], wB = wp[1];
#pragma unroll
                    for (int c = 0; c < 4; c++) {
                        ffma2(acc[0][c], wA.x, xb[kx + c]);
                        ffma2(acc[1][c], wA.y, xb[kx + c]);
                        ffma2(acc[2][c], wB.x, xb[kx + c]);
                        ffma2(acc[3][c], wB.y, xb[kx + c]);
                    }
                }
            }
        }
    }

    float bias[8];
    const float* bsrc = (co0 < 256) ? (cb + co0) : (qb + co0 - 256);
#pragma unroll
    for (int t = 0; t < 8; t++) bias[t] = bsrc[t];

    float v[8][4];
#pragma unroll
    for (int a = 0; a < 4; a++)
#pragma unroll
        for (int c = 0; c < 4; c++) {
            float lo, hi; upk2(lo, hi, acc[a][c]);
            v[2 * a][c]     = lo + bias[2 * a];
            v[2 * a + 1][c] = hi + bias[2 * a + 1];
        }

    const int base_pos = (y0 + ly) * 32 + lx0;
    if (co0 < 256) {
        // conv_out -> output channels [0,256)
#pragma unroll
        for (int cc = 0; cc < 8; cc++)
            *(float4*)&out[(size_t)(b * 512 + co0 + cc) * 1024 + base_pos] =
                make_float4(v[cc][0], v[cc][1], v[cc][2], v[cc][3]);
    } else {
        int qc0 = co0 - 256;
        int seg = qc0 >> 8;              // 0=q 1=k 2=v
        int c8  = qc0 & 255;
        int h = c8 >> 5, d0 = c8 & 31;
        float* dstb = (seg == 0 ? g_q : (seg == 1 ? g_k : g_v))
                      + (size_t)((b * 8 + h) * 1024) * 32 + d0;
        float scale = (seg == 0) ? QSCALE : 1.f;
#pragma unroll
        for (int c = 0; c < 4; c++) {
            int pos = base_pos + c;
            *(float4*)(dstb + (size_t)pos * 32) =
                make_float4(v[0][c] * scale, v[1][c] * scale, v[2][c] * scale, v[3][c] * scale);
            *(float4*)(dstb + (size_t)pos * 32 + 4) =
                make_float4(v[4][c] * scale, v[5][c] * scale, v[6][c] * scale, v[7][c] * scale);
        }
    }
}

// ---------------------------------------------------------------------------
// K2: rel-logit tables.
//   RX[bh][i][jc] = q_i . kr_x[jc - (i&31) + 31]
//   RY[bh][i][jr] = q_{(i&31)*32+(i>>5)} . kr_y[jr - (i&31) + 31]
// Block = (bh, 32-query group), 256 threads.
// ---------------------------------------------------------------------------
__global__ __launch_bounds__(256) void k_rel(const float* __restrict__ krx,
                                             const float* __restrict__ kry) {
    __shared__ float KX[63 * 33], KY[63 * 33], QR[32 * 32], QT[32 * 32];
    const int bh = blockIdx.x, qg = blockIdx.y, tid = threadIdx.x;

    for (int t = tid; t < 63 * 32; t += 256) {
        int m = t >> 5, d = t & 31;
        KX[m * 33 + d] = krx[t];
        KY[m * 33 + d] = kry[t];
    }
    for (int t = tid; t < 1024; t += 256) {
        int il = t >> 5, d = t & 31;
        QR[t] = g_q[(size_t)(bh * 1024 + qg * 32 + il) * 32 + d];
        QT[t] = g_q[(size_t)(bh * 1024 + il * 32 + qg) * 32 + d];   // transposed position
    }
    __syncthreads();

    const int wid = tid >> 5, j = tid & 31;
#pragma unroll
    for (int r = 0; r < 4; r++) {
        int il = r * 8 + wid;
        int m = j - il + 31;                 // in [0,62]
        float ax = 0.f, ay = 0.f;
#pragma unroll
        for (int d = 0; d < 32; d++) {
            ax += QR[il * 32 + d] * KX[m * 33 + d];
            ay += QT[il * 32 + d] * KY[m * 33 + d];
        }
        int i = qg * 32 + il;
        g_rx[(size_t)(bh * 1024 + i) * 32 + j] = ax;
        g_ry[(size_t)(bh * 1024 + i) * 32 + j] = ay;
    }
}

// ---------------------------------------------------------------------------
// K3: flash attention per (bh). Block = (bh, 64-query tile), 64 threads,
// one query per thread. Key tiles of 32, online softmax, f32x2 over d-pairs.
// ---------------------------------------------------------------------------
__global__ __launch_bounds__(64) void k_attn() {
    __shared__ __align__(16) float Ks[32 * 32];
    __shared__ __align__(16) float Vs[32 * 32];
    __shared__ float RXs[64 * 33], RYs[64 * 33];

    const int bh = blockIdx.x, qt = blockIdx.y, tid = threadIdx.x;
    const int i = qt * 64 + tid;

    u64 q2[16];
    {
        const ulonglong2* qp = (const ulonglong2*)(g_q + (size_t)(bh * 1024 + i) * 32);
#pragma unroll
        for (int t = 0; t < 8; t++) { ulonglong2 vv = qp[t]; q2[2 * t] = vv.x; q2[2 * t + 1] = vv.y; }
    }
    for (int t = tid; t < 2048; t += 64) {
        int ql = t >> 5, j = t & 31;
        RXs[ql * 33 + j] = g_rx[(size_t)(bh * 1024 + qt * 64 + ql) * 32 + j];
        RYs[ql * 33 + j] = g_ry[(size_t)(bh * 1024 + qt * 64 + ql) * 32 + j];
    }

    float m = -1e30f, l = 0.f;
    u64 av[16];
#pragma unroll
    for (int t = 0; t < 16; t++) av[t] = 0ULL;

    for (int jt = 0; jt < 32; jt++) {
        __syncthreads();
        for (int t = tid; t < 512; t += 64) {
            int sel = t >> 8, r = (t & 255) >> 3, f = t & 7;
            const float* src = (sel ? g_v : g_k)
                               + (size_t)(bh * 1024 + jt * 32 + r) * 32 + f * 4;
            float4 vv = *(const float4*)src;
            *(float4*)((sel ? Vs : Ks) + r * 32 + f * 4) = vv;
        }
        __syncthreads();

        const float ry = RYs[tid * 33 + jt];
        float s[32];
#pragma unroll
        for (int j = 0; j < 32; j++) {
            u64 a2 = 0ULL;
            const ulonglong2* kp = (const ulonglong2*)(Ks + j * 32);
#pragma unroll
            for (int t2 = 0; t2 < 8; t2++) {
                ulonglong2 kv = kp[t2];
                ffma2(a2, q2[2 * t2], kv.x);
                ffma2(a2, q2[2 * t2 + 1], kv.y);
            }
            float lo, hi; upk2(lo, hi, a2);
            s[j] = lo + hi + RXs[tid * 33 + j] + ry;
        }

        float mt = s[0];
#pragma unroll
        for (int j = 1; j < 32; j++) mt = fmaxf(mt, s[j]);
        float mnew = fmaxf(m, mt);
        float sc = __expf(m - mnew);
        l *= sc;
        u64 sc2 = pk2(sc, sc);
#pragma unroll
        for (int t2 = 0; t2 < 16; t2++) av[t2] = fmul2(av[t2], sc2);

#pragma unroll
        for (int j = 0; j < 32; j++) {
            float p = __expf(s[j] - mnew);
            l += p;
            u64 p2 = pk2(p, p);
            const ulonglong2* vp = (const ulonglong2*)(Vs + j * 32);
#pragma unroll
            for (int t2 = 0; t2 < 8; t2++) {
                ulonglong2 vv = vp[t2];
                ffma2(av[2 * t2],     p2, vv.x);
                ffma2(av[2 * t2 + 1], p2, vv.y);
            }
        }
        m = mnew;
    }

    // epilogue: divide by l, write with the reference's "raw reshape" scrambling:
    // channel = h*32 + (i>>5), pos = (i&31)*32 + d
    float inv = 1.0f / l;
    u64 inv2 = pk2(inv, inv);
    int b = bh >> 3, h = bh & 7;
    float* dst = g_att + (size_t)(b * 256 + h * 32 + (i >> 5)) * 1024 + (i & 31) * 32;
#pragma unroll
    for (int t = 0; t < 8; t++) {
        float a0, a1, a2, a3;
        u64 r0 = fmul2(av[2 * t], inv2), r1 = fmul2(av[2 * t + 1], inv2);
        upk2(a0, a1, r0); upk2(a2, a3, r1);
        ((float4*)dst)[t] = make_float4(a0, a1, a2, a3);
    }
}

// ---------------------------------------------------------------------------
// K4: 1x1 projection of attention output -> output channels [256,512)
// Block: 64 co x 64 pos, 256 threads, tile 4co x 4pos.
// ---------------------------------------------------------------------------
__global__ __launch_bounds__(256) void k_proj(const float* __restrict__ aw,
                                              const float* __restrict__ ab,
                                              float* __restrict__ out) {
    __shared__ float As[64 * 68];
    __shared__ float Wt[64 * 65];
    const int bx = blockIdx.x;
    const int b = bx >> 4;
    const int pos0 = (bx & 15) * 64;
    const int co0 = blockIdx.y * 64;
    const int tid = threadIdx.x;
    const int cg = tid >> 4, pg = tid & 15;
    const int col0 = cg * 4, pl0 = pg * 4;

    float acc[4][4] = {};

    for (int cc = 0; cc < 4; cc++) {
        const int ci0 = cc * 64;
        __syncthreads();
        for (int t = tid; t < 1024; t += 256) {
            int rl = t >> 4, f = t & 15;
            *(float4*)&As[rl * 68 + f * 4] =
                *(const float4*)&g_att[(size_t)(b * 256 + ci0 + rl) * 1024 + pos0 + f * 4];
            float4 wv = *(const float4*)&aw[(co0 + rl) * 256 + ci0 + f * 4];
            Wt[(f * 4 + 0) * 65 + rl] = wv.x;
            Wt[(f * 4 + 1) * 65 + rl] = wv.y;
            Wt[(f * 4 + 2) * 65 + rl] = wv.z;
            Wt[(f * 4 + 3) * 65 + rl] = wv.w;
        }
        __syncthreads();
#pragma unroll 8
        for (int k = 0; k < 64; k++) {
            float wv[4], avv[4];
#pragma unroll
            for (int t = 0; t < 4; t++) wv[t]  = Wt[k * 65 + col0 + t];
#pragma unroll
            for (int t = 0; t < 4; t++) avv[t] = As[k * 68 + pl0 + t];
#pragma unroll
            for (int a = 0; a < 4; a++)
#pragma unroll
                for (int p = 0; p < 4; p++) acc[a][p] += wv[a] * avv[p];
        }
    }

#pragma unroll
    for (int a = 0; a < 4; a++) {
        int co = co0 + col0 + a;
        float bb = ab[co];
        *(float4*)&out[(size_t)(b * 512 + 256 + co) * 1024 + pos0 + pl0] =
            make_float4(acc[a][0] + bb, acc[a][1] + bb, acc[a][2] + bb, acc[a][3] + bb);
    }
}

// ---------------------------------------------------------------------------
extern "C" void kernel_launch(void* const* d_in, const int* in_sizes, int n_in,
                              void* d_out, int out_size) {
    const float* x   = (const float*)d_in[0];
    const float* cw  = (const float*)d_in[1];
    const float* cb  = (const float*)d_in[2];
    const float* qw  = (const float*)d_in[3];
    const float* qb  = (const float*)d_in[4];
    const float* aw  = (const float*)d_in[5];
    const float* ab  = (const float*)d_in[6];
    const float* krx = (const float*)d_in[7];
    const float* kry = (const float*)d_in[8];
    float* out = (float*)d_out;

    k_wt  <<<4608, 256>>>(cw, qw);
    k_conv<<<dim3(64, 8), 256>>>(x, cb, qb, out);
    k_rel <<<dim3(32, 32), 256>>>(krx, kry);
    k_attn<<<dim3(32, 16), 64>>>();
    k_proj<<<dim3(64, 4), 256>>>(aw, ab, out);
}